// round 12
// baseline (speedup 1.0000x reference)
#include <cuda_runtime.h>
#include <math.h>

#define EPSV 1e-06f
#define BLK 256

struct Sim3 {
    float tx, ty, tz;
    float qx, qy, qz, qw;
    float s;
};

__device__ __forceinline__ Sim3 load_sim3(const float* __restrict__ p) {
    float4 a = *reinterpret_cast<const float4*>(p);
    float4 b = *reinterpret_cast<const float4*>(p + 4);
    Sim3 T;
    T.tx = a.x; T.ty = a.y; T.tz = a.z;
    T.qx = a.w; T.qy = b.x; T.qz = b.y; T.qw = b.z;
    T.s  = b.w;
    return T;
}

__device__ __forceinline__ Sim3 load_sim3_smem(const float* p) {
    float4 a = *reinterpret_cast<const float4*>(p);
    float4 b = *reinterpret_cast<const float4*>(p + 4);
    Sim3 T;
    T.tx = a.x; T.ty = a.y; T.tz = a.z;
    T.qx = a.w; T.qy = b.x; T.qz = b.y; T.qw = b.z;
    T.s  = b.w;
    return T;
}

// fast atan2 for y >= 0; |error| ~1e-5 rad
__device__ __forceinline__ float fast_atan2_pos(float y, float x) {
    float ax = fabsf(x);
    float mn = fminf(ax, y);
    float mx = fmaxf(ax, y);
    float a  = __fdividef(mn, mx);
    float s  = a * a;
    float r  = fmaf(fmaf(fmaf(fmaf(0.0208351f, s, -0.0851330f), s,
                              0.1801410f), s, -0.3302995f), s, 0.9998660f) * a;
    if (y > ax)   r = 1.5707963268f - r;
    if (x < 0.0f) r = 3.1415926536f - r;
    return r;
}

__device__ __forceinline__ void quat_rotate(float qx, float qy, float qz, float qw,
                                            float vx, float vy, float vz,
                                            float& ox, float& oy, float& oz) {
    float ux = qy * vz - qz * vy;
    float uy = qz * vx - qx * vz;
    float uz = qx * vy - qy * vx;
    float wx = qy * uz - qz * uy;
    float wy = qz * ux - qx * uz;
    float wz = qx * uy - qy * ux;
    ox = vx + 2.0f * (qw * ux + wx);
    oy = vy + 2.0f * (qw * uy + wy);
    oz = vz + 2.0f * (qw * uz + wz);
}

// Fused sim3_mul(sim3_inv(T1), T2)
__device__ __forceinline__ Sim3 sim3_inv_mul(const Sim3& T1, const Sim3& T2) {
    float cx = -T1.qx, cy = -T1.qy, cz = -T1.qz, cw = T1.qw;
    float s_inv = __fdividef(1.0f, T1.s);

    float dx = T2.tx - T1.tx;
    float dy = T2.ty - T1.ty;
    float dz = T2.tz - T1.tz;
    float rx, ry, rz;
    quat_rotate(cx, cy, cz, cw, dx, dy, dz, rx, ry, rz);

    Sim3 R;
    R.tx = s_inv * rx; R.ty = s_inv * ry; R.tz = s_inv * rz;
    float x2 = T2.qx, y2 = T2.qy, z2 = T2.qz, w2 = T2.qw;
    R.qx = cw * x2 + cx * w2 + cy * z2 - cz * y2;
    R.qy = cw * y2 - cx * z2 + cy * w2 + cz * x2;
    R.qz = cw * z2 + cx * y2 - cy * x2 + cz * w2;
    R.qw = cw * w2 - cx * x2 - cy * y2 - cz * z2;
    R.s = s_inv * T2.s;
    return R;
}

__device__ __forceinline__ Sim3 sim3_mul(const Sim3& A, const Sim3& B) {
    Sim3 R;
    float rx, ry, rz;
    quat_rotate(A.qx, A.qy, A.qz, A.qw, B.tx, B.ty, B.tz, rx, ry, rz);
    R.tx = A.tx + A.s * rx;
    R.ty = A.ty + A.s * ry;
    R.tz = A.tz + A.s * rz;
    float x1 = A.qx, y1 = A.qy, z1 = A.qz, w1 = A.qw;
    float x2 = B.qx, y2 = B.qy, z2 = B.qz, w2 = B.qw;
    R.qx = w1 * x2 + x1 * w2 + y1 * z2 - z1 * y2;
    R.qy = w1 * y2 - x1 * z2 + y1 * w2 + z1 * x2;
    R.qz = w1 * z2 + x1 * y2 - y1 * x2 + z1 * w2;
    R.qw = w1 * w2 - x1 * x2 - y1 * y2 - z1 * z2;
    R.s = A.s * B.s;
    return R;
}

// out[7] = [tau(3), phi(3), sigma]
__device__ __forceinline__ void sim3_log(const Sim3& T, float out[7]) {
    float nv2 = T.qx * T.qx + T.qy * T.qy + T.qz * T.qz;
    float nv = (nv2 > 0.0f) ? nv2 * __frsqrt_rn(nv2) : 0.0f;
    float theta_r = 2.0f * fast_atan2_pos(nv, T.qw);
    bool small_r = nv < EPSV;
    float fac = small_r ? 2.0f : __fdividef(theta_r, nv);
    float px = fac * T.qx, py = fac * T.qy, pz = fac * T.qz;

    float sigma = __logf(T.s);
    float theta = fac * nv;   // == ||phi|| exactly

    bool sig_small = fabsf(sigma) < EPSV;
    bool th_small  = theta < EPSV;
    float sg = sig_small ? 1.0f : sigma;
    float th = th_small ? 1.0f : theta;

    float scale = T.s;        // exp(log(s)) == s
    float th2 = th * th;
    float sg2 = sg * sg;

    float C = sig_small ? 1.0f : __fdividef(scale - 1.0f, sg);

    float sth, cth;
    __sincosf(th, &sth, &cth);

    float c      = th2 + sg2;
    float inv_c  = __fdividef(1.0f, c);
    float inv_th = __fdividef(1.0f, th);
    float inv_th2 = inv_th * inv_th;

    float a = scale * sth;
    float b = scale * cth;
    float A_g = (a * sg + (1.0f - b) * th) * inv_th * inv_c;
    float B_g = (C - ((b - 1.0f) * sg + a * th) * inv_c) * inv_th2;
    float A_ss = th_small ? 0.5f : (1.0f - cth) * inv_th2;
    float B_ss = th_small ? (1.0f / 6.0f) : (th - sth) * inv_th2 * inv_th;
    float A_ts = __fdividef((sg - 1.0f) * scale + 1.0f, sg2);
    float B_ts = __fdividef(scale * (sg2 - 2.0f * sg + 2.0f) - 2.0f, 2.0f * sg2 * sg);

    float A = sig_small ? A_ss : (th_small ? A_ts : A_g);
    float B = sig_small ? B_ss : (th_small ? B_ts : B_g);

    // W^-1 = x*I + y*Phi + z*Phi^2 (Phi^3 = -|phi|^2 Phi)
    float t2t = theta * theta;
    float P = C - t2t * B;
    float det2 = P * P + t2t * (A * A);
    float invC = __fdividef(1.0f, C);
    float invd = __fdividef(1.0f, det2);
    float y = -A * invd;
    float z = (A * A - P * B) * invC * invd;

    float tx = T.tx, ty = T.ty, tz = T.tz;
    float ux = py * tz - pz * ty;
    float uy = pz * tx - px * tz;
    float uz = px * ty - py * tx;
    float vx = py * uz - pz * uy;
    float vy = pz * ux - px * uz;
    float vz = px * uy - py * ux;

    out[0] = invC * tx + y * ux + z * vx;
    out[1] = invC * ty + y * uy + z * vy;
    out[2] = invC * tz + y * uz + z * vz;
    out[3] = px;
    out[4] = py;
    out[5] = pz;
    out[6] = sigma;
}

__global__ void pgo_kernel(const float* __restrict__ Twc,
                           const float* __restrict__ Twc_prior_inv,
                           const float* __restrict__ Todom_inv,
                           const float* __restrict__ prior_weight,
                           const float* __restrict__ odom_weight,
                           const int*   __restrict__ edges,
                           const float* __restrict__ T_lc,
                           float* __restrict__ out,
                           int n) {
    // smem staging: all sequential-stream arrays, block-coalesced
    __shared__ float s_twc[(BLK + 1) * 8];  // rows i0 .. i0+BLK (need i+1)
    __shared__ float s_pri[BLK * 8];
    __shared__ float s_odo[BLK * 8];
    __shared__ float s_pw[BLK * 7];
    __shared__ float s_ow[BLK * 7];

    int tid = threadIdx.x;
    int i0 = blockIdx.x * BLK;
    int i = i0 + tid;

    int rows   = min(BLK, n - i0);          // valid residual rows in block
    int rows_t = min(BLK + 1, (n + 1) - i0); // valid Twc rows

    // ---- coalesced float4 burst loads into smem ----
    {
        float4* d = reinterpret_cast<float4*>(s_twc);
        const float4* s = reinterpret_cast<const float4*>(Twc + 8 * (size_t)i0);
        int cnt = 2 * rows_t;
        for (int j = tid; j < cnt; j += BLK) d[j] = s[j];
    }
    {
        float4* d = reinterpret_cast<float4*>(s_pri);
        const float4* s = reinterpret_cast<const float4*>(Twc_prior_inv + 8 * (size_t)i0);
        int cnt = 2 * rows;
        for (int j = tid; j < cnt; j += BLK) d[j] = s[j];
    }
    {
        float4* d = reinterpret_cast<float4*>(s_odo);
        const float4* s = reinterpret_cast<const float4*>(Todom_inv + 8 * (size_t)i0);
        int cnt = 2 * rows;
        for (int j = tid; j < cnt; j += BLK) d[j] = s[j];
    }
    {
        int lim = 7 * rows;                   // floats valid
        const float* sp = prior_weight + 7 * (size_t)i0;
        const float* so = odom_weight + 7 * (size_t)i0;
        int vec = lim >> 2;                   // full float4s
        float4* dp = reinterpret_cast<float4*>(s_pw);
        float4* dw = reinterpret_cast<float4*>(s_ow);
        const float4* spv = reinterpret_cast<const float4*>(sp);
        const float4* sov = reinterpret_cast<const float4*>(so);
        for (int j = tid; j < vec; j += BLK) { dp[j] = spv[j]; dw[j] = sov[j]; }
        for (int j = 4 * vec + tid; j < lim; j += BLK) { s_pw[j] = sp[j]; s_ow[j] = so[j]; }
    }
    __syncthreads();

    if (i >= n) return;

    // random gathers + T_lc stay direct (coalesced / latency overlapped with math)
    int2 e = *reinterpret_cast<const int2*>(edges + 2 * (size_t)i);
    Sim3 Ta = load_sim3(Twc + 8 * (size_t)e.x);
    Sim3 Tb = load_sim3(Twc + 8 * (size_t)e.y);
    Sim3 Tl = load_sim3(T_lc + 8 * (size_t)i);

    Sim3 Ti = load_sim3_smem(s_twc + 8 * tid);
    Sim3 Tj = load_sim3_smem(s_twc + 8 * (tid + 1));
    Sim3 delta = sim3_inv_mul(Ti, Tj);

    float r_prior[7], r_odom[7], r_lc[7];

    Sim3 Tp = load_sim3_smem(s_pri + 8 * tid);
    sim3_log(sim3_mul(delta, Tp), r_prior);

    Sim3 To = load_sim3_smem(s_odo + 8 * tid);
    sim3_log(sim3_mul(delta, To), r_odom);

    Sim3 delta_lc = sim3_inv_mul(Ta, Tb);
    sim3_log(sim3_mul(delta_lc, Tl), r_lc);

    const float* pw = s_pw + 7 * tid;
    const float* ow = s_ow + 7 * tid;
    float* o = out + 7 * (size_t)i;
    #pragma unroll
    for (int k = 0; k < 7; k++) {
        o[k] = fmaf(r_prior[k], pw[k], fmaf(r_odom[k], ow[k], r_lc[k]));
    }
}

extern "C" void kernel_launch(void* const* d_in, const int* in_sizes, int n_in,
                              void* d_out, int out_size) {
    const float* Twc           = (const float*)d_in[0];
    const float* Twc_prior_inv = (const float*)d_in[1];
    const float* Todom_inv     = (const float*)d_in[2];
    const float* prior_weight  = (const float*)d_in[3];
    const float* odom_weight   = (const float*)d_in[4];
    const int*   edges         = (const int*)d_in[5];
    const float* T_lc          = (const float*)d_in[6];
    float* out = (float*)d_out;

    int n = out_size / 7;

    int blocks = (n + BLK - 1) / BLK;
    pgo_kernel<<<blocks, BLK>>>(Twc, Twc_prior_inv, Todom_inv,
                                prior_weight, odom_weight, edges, T_lc,
                                out, n);
}

// round 13
// speedup vs baseline: 1.6081x; 1.6081x over previous
#include <cuda_runtime.h>
#include <math.h>

#define EPSV 1e-06f

struct Sim3 {
    float tx, ty, tz;
    float qx, qy, qz, qw;
    float s;
};

__device__ __forceinline__ Sim3 load_sim3(const float* __restrict__ p) {
    float4 a = *reinterpret_cast<const float4*>(p);
    float4 b = *reinterpret_cast<const float4*>(p + 4);
    Sim3 T;
    T.tx = a.x; T.ty = a.y; T.tz = a.z;
    T.qx = a.w; T.qy = b.x; T.qz = b.y; T.qw = b.z;
    T.s  = b.w;
    return T;
}

// fast atan2 for y >= 0; |error| ~1e-5 rad
__device__ __forceinline__ float fast_atan2_pos(float y, float x) {
    float ax = fabsf(x);
    float mn = fminf(ax, y);
    float mx = fmaxf(ax, y);
    float a  = __fdividef(mn, mx);
    float s  = a * a;
    float r  = fmaf(fmaf(fmaf(fmaf(0.0208351f, s, -0.0851330f), s,
                              0.1801410f), s, -0.3302995f), s, 0.9998660f) * a;
    if (y > ax)   r = 1.5707963268f - r;
    if (x < 0.0f) r = 3.1415926536f - r;
    return r;
}

__device__ __forceinline__ void quat_rotate(float qx, float qy, float qz, float qw,
                                            float vx, float vy, float vz,
                                            float& ox, float& oy, float& oz) {
    float ux = qy * vz - qz * vy;
    float uy = qz * vx - qx * vz;
    float uz = qx * vy - qy * vx;
    float wx = qy * uz - qz * uy;
    float wy = qz * ux - qx * uz;
    float wz = qx * uy - qy * ux;
    ox = vx + 2.0f * (qw * ux + wx);
    oy = vy + 2.0f * (qw * uy + wy);
    oz = vz + 2.0f * (qw * uz + wz);
}

// Fused sim3_mul(sim3_inv(T1), T2)
__device__ __forceinline__ Sim3 sim3_inv_mul(const Sim3& T1, const Sim3& T2) {
    float cx = -T1.qx, cy = -T1.qy, cz = -T1.qz, cw = T1.qw;
    float s_inv = __fdividef(1.0f, T1.s);

    float dx = T2.tx - T1.tx;
    float dy = T2.ty - T1.ty;
    float dz = T2.tz - T1.tz;
    float rx, ry, rz;
    quat_rotate(cx, cy, cz, cw, dx, dy, dz, rx, ry, rz);

    Sim3 R;
    R.tx = s_inv * rx; R.ty = s_inv * ry; R.tz = s_inv * rz;
    float x2 = T2.qx, y2 = T2.qy, z2 = T2.qz, w2 = T2.qw;
    R.qx = cw * x2 + cx * w2 + cy * z2 - cz * y2;
    R.qy = cw * y2 - cx * z2 + cy * w2 + cz * x2;
    R.qz = cw * z2 + cx * y2 - cy * x2 + cz * w2;
    R.qw = cw * w2 - cx * x2 - cy * y2 - cz * z2;
    R.s = s_inv * T2.s;
    return R;
}

__device__ __forceinline__ Sim3 sim3_mul(const Sim3& A, const Sim3& B) {
    Sim3 R;
    float rx, ry, rz;
    quat_rotate(A.qx, A.qy, A.qz, A.qw, B.tx, B.ty, B.tz, rx, ry, rz);
    R.tx = A.tx + A.s * rx;
    R.ty = A.ty + A.s * ry;
    R.tz = A.tz + A.s * rz;
    float x1 = A.qx, y1 = A.qy, z1 = A.qz, w1 = A.qw;
    float x2 = B.qx, y2 = B.qy, z2 = B.qz, w2 = B.qw;
    R.qx = w1 * x2 + x1 * w2 + y1 * z2 - z1 * y2;
    R.qy = w1 * y2 - x1 * z2 + y1 * w2 + z1 * x2;
    R.qz = w1 * z2 + x1 * y2 - y1 * x2 + z1 * w2;
    R.qw = w1 * w2 - x1 * x2 - y1 * y2 - z1 * z2;
    R.s = A.s * B.s;
    return R;
}

// out[7] = [tau(3), phi(3), sigma]
__device__ __forceinline__ void sim3_log(const Sim3& T, float out[7]) {
    float qw = T.qw;
    float nv2 = T.qx * T.qx + T.qy * T.qy + T.qz * T.qz;
    float nv = (nv2 > 0.0f) ? nv2 * __frsqrt_rn(nv2) : 0.0f;

    // sin/cos of theta = 2*atan2(nv, qw) directly from the quaternion
    // (valid in all quadrants; quats are unit up to rounding, but divide
    //  by n2 anyway for robustness). Independent of the atan2 chain.
    float qw2 = qw * qw;
    float n2 = nv2 + qw2;
    float inv_n2 = __fdividef(1.0f, n2);
    float cth = (qw2 - nv2) * inv_n2;
    float sth = 2.0f * qw * nv * inv_n2;

    float theta_r = 2.0f * fast_atan2_pos(nv, qw);
    bool small_r = nv < EPSV;
    float fac = small_r ? 2.0f : __fdividef(theta_r, nv);
    float px = fac * T.qx, py = fac * T.qy, pz = fac * T.qz;

    float sigma = __logf(T.s);
    float theta = fac * nv;   // == ||phi|| exactly

    bool sig_small = fabsf(sigma) < EPSV;
    bool th_small  = theta < EPSV;
    float sg = sig_small ? 1.0f : sigma;
    float th = th_small ? 1.0f : theta;

    float scale = T.s;        // exp(log(s)) == s
    float th2 = th * th;
    float sg2 = sg * sg;

    float C = sig_small ? 1.0f : __fdividef(scale - 1.0f, sg);

    float c      = th2 + sg2;
    float inv_c  = __fdividef(1.0f, c);
    float inv_th = __fdividef(1.0f, th);
    float inv_th2 = inv_th * inv_th;

    float a = scale * sth;
    float b = scale * cth;
    float A_g = (a * sg + (1.0f - b) * th) * inv_th * inv_c;
    float B_g = (C - ((b - 1.0f) * sg + a * th) * inv_c) * inv_th2;
    float A_ss = th_small ? 0.5f : (1.0f - cth) * inv_th2;
    float B_ss = th_small ? (1.0f / 6.0f) : (th - sth) * inv_th2 * inv_th;
    float A_ts = __fdividef((sg - 1.0f) * scale + 1.0f, sg2);
    float B_ts = __fdividef(scale * (sg2 - 2.0f * sg + 2.0f) - 2.0f, 2.0f * sg2 * sg);

    float A = sig_small ? A_ss : (th_small ? A_ts : A_g);
    float B = sig_small ? B_ss : (th_small ? B_ts : B_g);

    // W^-1 = x*I + y*Phi + z*Phi^2 (Phi^3 = -|phi|^2 Phi)
    float t2t = theta * theta;
    float P = C - t2t * B;
    float det2 = P * P + t2t * (A * A);
    float invC = __fdividef(1.0f, C);
    float invd = __fdividef(1.0f, det2);
    float y = -A * invd;
    float z = (A * A - P * B) * invC * invd;

    float tx = T.tx, ty = T.ty, tz = T.tz;
    float ux = py * tz - pz * ty;
    float uy = pz * tx - px * tz;
    float uz = px * ty - py * tx;
    float vx = py * uz - pz * uy;
    float vy = pz * ux - px * uz;
    float vz = px * uy - py * ux;

    out[0] = invC * tx + y * ux + z * vx;
    out[1] = invC * ty + y * uy + z * vy;
    out[2] = invC * tz + y * uz + z * vz;
    out[3] = px;
    out[4] = py;
    out[5] = pz;
    out[6] = sigma;
}

__global__ __launch_bounds__(256)
void pgo_kernel(const float* __restrict__ Twc,
                const float* __restrict__ Twc_prior_inv,
                const float* __restrict__ Todom_inv,
                const float* __restrict__ prior_weight,
                const float* __restrict__ odom_weight,
                const int*   __restrict__ edges,
                const float* __restrict__ T_lc,
                float* __restrict__ out,
                int n) {
    unsigned i = blockIdx.x * blockDim.x + threadIdx.x;
    if (i >= (unsigned)n) return;

    // issue the random gather first so its latency overlaps the math below
    int2 e = *reinterpret_cast<const int2*>(edges + 2u * i);
    Sim3 Ta = load_sim3(Twc + 8u * (unsigned)e.x);
    Sim3 Tb = load_sim3(Twc + 8u * (unsigned)e.y);
    Sim3 Tl = load_sim3(T_lc + 8u * i);

    Sim3 Ti  = load_sim3(Twc + 8u * i);
    Sim3 Tj  = load_sim3(Twc + 8u * (i + 1u));
    Sim3 delta = sim3_inv_mul(Ti, Tj);

    float r_prior[7], r_odom[7], r_lc[7];

    Sim3 Tp = load_sim3(Twc_prior_inv + 8u * i);
    sim3_log(sim3_mul(delta, Tp), r_prior);

    Sim3 To = load_sim3(Todom_inv + 8u * i);
    sim3_log(sim3_mul(delta, To), r_odom);

    Sim3 delta_lc = sim3_inv_mul(Ta, Tb);
    sim3_log(sim3_mul(delta_lc, Tl), r_lc);

    const float* pw = prior_weight + 7u * i;
    const float* ow = odom_weight + 7u * i;
    float* o = out + 7u * i;
    #pragma unroll
    for (int k = 0; k < 7; k++) {
        o[k] = fmaf(r_prior[k], pw[k], fmaf(r_odom[k], ow[k], r_lc[k]));
    }
}

extern "C" void kernel_launch(void* const* d_in, const int* in_sizes, int n_in,
                              void* d_out, int out_size) {
    const float* Twc           = (const float*)d_in[0];
    const float* Twc_prior_inv = (const float*)d_in[1];
    const float* Todom_inv     = (const float*)d_in[2];
    const float* prior_weight  = (const float*)d_in[3];
    const float* odom_weight   = (const float*)d_in[4];
    const int*   edges         = (const int*)d_in[5];
    const float* T_lc          = (const float*)d_in[6];
    float* out = (float*)d_out;

    int n = out_size / 7;

    int threads = 256;
    int blocks = (n + threads - 1) / threads;
    pgo_kernel<<<blocks, threads>>>(Twc, Twc_prior_inv, Todom_inv,
                                    prior_weight, odom_weight, edges, T_lc,
                                    out, n);
}